// round 2
// baseline (speedup 1.0000x reference)
#include <cuda_runtime.h>
#include <math_constants.h>
#include <cstdint>

#define NB 8
#define LL 1024
#define KNB 30
#define NRBF 16
#define EF 128
#define EIN 416
#define MAXREL 32

// Output layout (floats): h_V zeros | E | E_idx(float)
#define OFF_E    (NB*LL*EF)                       // 1,048,576
#define OFF_EIDX (OFF_E + (size_t)NB*LL*KNB*EF)   // 32,505,856

__device__ float g_Cb[NB*LL*3];
__device__ int   g_Eidx[NB*LL*KNB];
__device__ float g_Dn[NB*LL*KNB];

// atom codes: 0=N,1=Ca,2=C,3=O,4=Cb ; 24 pairs (A at i, B at j)
__constant__ int c_pa[24] = {0,2,3,4,1,1,1,1,0,0,0,4,4,3,0,2,3,4,2,3,4,2,3,2};
__constant__ int c_pb[24] = {0,2,3,4,0,2,3,4,2,3,4,2,3,2,1,1,1,1,0,0,0,4,4,3};

__global__ void zero_hv_kernel(float4* out) {
    int i = blockIdx.x * blockDim.x + threadIdx.x;
    if (i < NB*LL*EF/4) out[i] = make_float4(0.f,0.f,0.f,0.f);
}

__global__ void cb_kernel(const float* __restrict__ X) {
    int i = blockIdx.x * blockDim.x + threadIdx.x;
    if (i >= NB*LL) return;
    const float* x = X + (size_t)i * 12;
    float bx = x[3]-x[0], by = x[4]-x[1], bz = x[5]-x[2];
    float cx = x[6]-x[3], cy = x[7]-x[4], cz = x[8]-x[5];
    float ax = by*cz - bz*cy;
    float ay = bz*cx - bx*cz;
    float az = bx*cy - by*cx;
    g_Cb[i*3+0] = -0.58273431f*ax + 0.56802827f*bx - 0.54067466f*cx + x[3];
    g_Cb[i*3+1] = -0.58273431f*ay + 0.56802827f*by - 0.54067466f*cy + x[4];
    g_Cb[i*3+2] = -0.58273431f*az + 0.56802827f*bz - 0.54067466f*cz + x[5];
}

// ---------------- top-k: one WARP per row, keys in registers ----------------
// key = (ordered_float_bits(D_adjust) << 32) | j  -> unique, lexicographic
// (value asc, index asc) == jax.lax.top_k(-D) ordering.
__global__ void __launch_bounds__(256) topk_kernel(const float* __restrict__ X,
                                                   const float* __restrict__ mask,
                                                   float* __restrict__ out) {
    __shared__ float sx[LL], sy[LL], sz[LL], smk[LL];
    int tid = threadIdx.x;
    int rowBase = blockIdx.x * 8;          // 8 rows (warps) per block
    int bb = rowBase >> 10;                // same batch for all 8 rows

    for (int j = tid; j < LL; j += 256) {
        const float* x = X + (size_t)(bb*LL + j) * 12;
        sx[j] = x[3]; sy[j] = x[4]; sz[j] = x[5];
        smk[j] = mask[bb*LL + j];
    }
    __syncthreads();

    int wid = tid >> 5, lane = tid & 31;
    int row = rowBase + wid;
    int i = row & 1023;
    float cx = sx[i], cy = sy[i], cz = sz[i], mi = smk[i];

    float D[32];
    float lmax = -CUDART_INF_F;
    #pragma unroll
    for (int q = 0; q < 32; q++) {
        int j = q*32 + lane;
        float dx = sx[j]-cx, dy = sy[j]-cy, dz = sz[j]-cz;
        float Dv = mi * smk[j] * sqrtf(dx*dx + dy*dy + dz*dz + 1e-6f);
        D[q] = Dv;
        lmax = fmaxf(lmax, Dv);
    }
    #pragma unroll
    for (int o = 16; o; o >>= 1)
        lmax = fmaxf(lmax, __shfl_xor_sync(0xffffffffu, lmax, o));

    unsigned long long key[32];
    #pragma unroll
    for (int q = 0; q < 32; q++) {
        int j = q*32 + lane;
        float adj = D[q] + (1.0f - mi*smk[j]) * lmax;   // D_adjust >= 0
        key[q] = ((unsigned long long)__float_as_uint(adj) << 32) | (unsigned)j;
    }

    unsigned long long prevP1 = 0ull;   // require key >= prevP1
    for (int kn = 0; kn < KNB; kn++) {
        unsigned long long best = ~0ull;
        #pragma unroll
        for (int q = 0; q < 32; q++) {
            unsigned long long k = key[q];
            if (k >= prevP1 && k < best) best = k;
        }
        #pragma unroll
        for (int o = 16; o; o >>= 1) {
            unsigned long long other = __shfl_xor_sync(0xffffffffu, best, o);
            if (other < best) best = other;
        }
        if (lane == 0) {
            int j = (int)(best & 0xffffffffull);
            g_Eidx[row*KNB + kn] = j;
            g_Dn[row*KNB + kn]   = __uint_as_float((unsigned)(best >> 32));
            out[OFF_EIDX + (size_t)row*KNB + kn] = (float)j;
        }
        prevP1 = best + 1ull;
    }
}

__device__ __forceinline__ void load_atom(const float* __restrict__ X, int code, int gr,
                                          float& x, float& y, float& z) {
    if (code == 4) {
        const float* p = g_Cb + (size_t)gr*3;
        x = p[0]; y = p[1]; z = p[2];
    } else {
        const float* p = X + (size_t)gr*12 + code*3;
        x = p[0]; y = p[1]; z = p[2];
    }
}

#define FMA2(acc, w, e) asm("fma.rn.f32x2 %0, %1, %2, %0;" : "+l"(acc) : "l"(w), "l"(e))
#define PACK2(dst, s)   asm("mov.b64 %0, {%1, %1};" : "=l"(dst) : "r"(__float_as_uint(s)))

// ---------------- edge kernel: register-tiled matvec ----------------
// Block: 2 residues = 60 edges = 30 pairs (padded to 32). 256 threads.
// smem: ed[32 pairs][417 doubles] (padded) = 106,752 B
//       Wt[128 rows][132 floats] (transposed W chunk, padded) = 67,584 B
#define PAIRS_PAD 32
#define EDS 417
#define WT_PAD 132
#define ED_FLOATS (PAIRS_PAD*EDS*2)     // 26,688
#define SMEM_BYTES ((ED_FLOATS + 128*WT_PAD)*4)   // 174,336

__global__ void __launch_bounds__(256, 1) edge_kernel(
    const float* __restrict__ X,
    const int*   __restrict__ ridx,
    const int*   __restrict__ chain,
    const float* __restrict__ posW,
    const float* __restrict__ posb,
    const float* __restrict__ W,
    const float* __restrict__ gamma,
    const float* __restrict__ beta,
    float* __restrict__ out)
{
    extern __shared__ float smem[];
    float* Wt = smem + ED_FLOATS;
    int tid = threadIdx.x;
    int pr  = blockIdx.x;
    int rg0 = pr * 2;
    int bb  = rg0 >> 10;

    // ---- Phase A: RBF features (2 * 30 * 25 = 1500 tasks) ----
    for (int t = tid; t < 1500; t += 256) {
        int r   = t / 750;
        int rem = t - r*750;
        int kn  = rem / 25;
        int p   = rem - kn*25;
        int rg  = rg0 + r;
        int j   = g_Eidx[rg*KNB + kn];
        float d;
        if (p == 0) {
            d = g_Dn[rg*KNB + kn];
        } else {
            float ax, ay, az, bx, by, bz;
            load_atom(X, c_pa[p-1], rg, ax, ay, az);
            load_atom(X, c_pb[p-1], bb*LL + j, bx, by, bz);
            float dx = ax-bx, dy = ay-by, dz = az-bz;
            d = sqrtf(dx*dx + dy*dy + dz*dz + 1e-6f);
        }
        int cbase = 16 + p*16;
        int pp = r*15 + (kn >> 1), sub = kn & 1;
        float* dst = smem + (size_t)(pp*EDS + cbase)*2 + sub;
        #pragma unroll
        for (int m = 0; m < NRBF; m++) {
            float z = (d - (2.0f + 1.3333333333f*m)) * 0.8f;
            dst[2*m] = __expf(-z*z);
        }
    }
    // ---- Phase A2: positional features ----
    for (int t = tid; t < 60; t += 256) {
        int r  = t / 30;
        int kn = t - r*30;
        int rg = rg0 + r;
        int j  = g_Eidx[rg*KNB + kn];
        int gj = bb*LL + j;
        int dch = (chain[rg] == chain[gj]);
        int off = ridx[rg] - ridx[gj] + MAXREL;
        int dd  = dch ? min(max(off, 0), 2*MAXREL) : (2*MAXREL + 1);
        int pp = r*15 + (kn >> 1), sub = kn & 1;
        float* dst = smem + (size_t)(pp*EDS)*2 + sub;
        #pragma unroll
        for (int m = 0; m < 16; m++)
            dst[2*m] = posW[m*66 + dd] + posb[m];
    }

    // ---- Phase B: GEMM, K chunked by 128. thread = (fg: 32 x F=4, pg: 8 x P=4) ----
    int fg = tid >> 3;     // 0..31 -> features fg*4 .. fg*4+3
    int pg = tid & 7;      // 0..7  -> pairs pg*4 .. pg*4+3 (30 real of 32)
    unsigned long long acc[4][4];
    #pragma unroll
    for (int a = 0; a < 4; a++)
        #pragma unroll
        for (int b = 0; b < 4; b++) acc[a][b] = 0ull;

    const unsigned long long* edp[4];
    #pragma unroll
    for (int pu = 0; pu < 4; pu++)
        edp[pu] = (const unsigned long long*)smem + (size_t)(pg*4+pu)*EDS;

    for (int ch = 0; ch < 4; ch++) {
        int c0  = ch * 128;
        int csz = (ch == 3) ? 32 : 128;
        // load+transpose W chunk into Wt (coalesced LDG.128, ~2-way STS conflict)
        int n4 = 32 * csz;   // float4 count = 128f * csz / 4
        for (int idx = tid; idx < n4; idx += 256) {
            int f, q;
            if (csz == 128) { f = idx >> 5; q = idx & 31; }
            else            { f = idx >> 3; q = idx & 7; }
            float4 v = *(const float4*)(W + (size_t)f*EIN + c0 + 4*q);
            float* wcol = Wt + (size_t)(4*q)*WT_PAD + f;
            wcol[0*WT_PAD] = v.x;
            wcol[1*WT_PAD] = v.y;
            wcol[2*WT_PAD] = v.z;
            wcol[3*WT_PAD] = v.w;
        }
        __syncthreads();

        const float* wbase = Wt + fg*4;
        #pragma unroll 4
        for (int cc = 0; cc < csz; cc++) {
            float4 w4 = *(const float4*)(wbase + cc*WT_PAD);
            unsigned long long w0, w1, w2, w3;
            PACK2(w0, w4.x); PACK2(w1, w4.y); PACK2(w2, w4.z); PACK2(w3, w4.w);
            #pragma unroll
            for (int pu = 0; pu < 4; pu++) {
                unsigned long long e = edp[pu][c0 + cc];
                FMA2(acc[0][pu], w0, e);
                FMA2(acc[1][pu], w1, e);
                FMA2(acc[2][pu], w2, e);
                FMA2(acc[3][pu], w3, e);
            }
        }
        __syncthreads();
    }

    // ---- write per-edge outputs to smem (reuse ed region): sout[60][128] ----
    float* sout = smem;
    #pragma unroll
    for (int pu = 0; pu < 4; pu++) {
        int p2 = pg*4 + pu;
        if (p2 < 30) {
            #pragma unroll
            for (int fu = 0; fu < 4; fu++) {
                unsigned lo = (unsigned)(acc[fu][pu] & 0xffffffffull);
                unsigned hi = (unsigned)(acc[fu][pu] >> 32);
                int f = fg*4 + fu;
                sout[(2*p2    )*EF + f] = __uint_as_float(lo);
                sout[(2*p2 + 1)*EF + f] = __uint_as_float(hi);
            }
        }
    }
    __syncthreads();

    // ---- LayerNorm + store: 8 warps over 60 edges ----
    int wr = tid >> 5, lane = tid & 31;
    for (int e = wr; e < 60; e += 8) {
        float x0 = sout[e*EF + lane];
        float x1 = sout[e*EF + lane + 32];
        float x2 = sout[e*EF + lane + 64];
        float x3 = sout[e*EF + lane + 96];
        float s = x0 + x1 + x2 + x3;
        #pragma unroll
        for (int o = 16; o; o >>= 1) s += __shfl_xor_sync(0xffffffffu, s, o);
        float mu = s * (1.0f/128.0f);
        float d0 = x0-mu, d1 = x1-mu, d2 = x2-mu, d3 = x3-mu;
        float vs = d0*d0 + d1*d1 + d2*d2 + d3*d3;
        #pragma unroll
        for (int o = 16; o; o >>= 1) vs += __shfl_xor_sync(0xffffffffu, vs, o);
        float inv = 1.0f / sqrtf(vs * (1.0f/128.0f) + 1e-5f);
        int rr = e / 30, kn = e - rr*30;
        int rg = rg0 + rr;
        size_t base = OFF_E + ((size_t)rg*KNB + kn)*EF;
        out[base + lane     ] = d0*inv*gamma[lane     ] + beta[lane     ];
        out[base + lane + 32] = d1*inv*gamma[lane + 32] + beta[lane + 32];
        out[base + lane + 64] = d2*inv*gamma[lane + 64] + beta[lane + 64];
        out[base + lane + 96] = d3*inv*gamma[lane + 96] + beta[lane + 96];
    }
}

extern "C" void kernel_launch(void* const* d_in, const int* in_sizes, int n_in,
                              void* d_out, int out_size) {
    const float* X     = (const float*)d_in[0];
    const float* mask  = (const float*)d_in[1];
    const int*   ridx  = (const int*)  d_in[2];
    const int*   chain = (const int*)  d_in[3];
    const float* posW  = (const float*)d_in[4];
    const float* posb  = (const float*)d_in[5];
    const float* W     = (const float*)d_in[6];
    const float* gamma = (const float*)d_in[7];
    const float* beta  = (const float*)d_in[8];
    float* out = (float*)d_out;

    zero_hv_kernel<<<(NB*LL*EF/4 + 255)/256, 256>>>((float4*)out);
    cb_kernel<<<(NB*LL + 255)/256, 256>>>(X);
    topk_kernel<<<NB*LL/8, 256>>>(X, mask, out);

    static bool attr_set = false;
    if (!attr_set) {
        cudaFuncSetAttribute(edge_kernel, cudaFuncAttributeMaxDynamicSharedMemorySize, SMEM_BYTES);
        attr_set = true;
    }
    edge_kernel<<<NB*LL/2, 256, SMEM_BYTES>>>(X, ridx, chain, posW, posb, W, gamma, beta, out);
}

// round 4
// speedup vs baseline: 1.2185x; 1.2185x over previous
#include <cuda_runtime.h>
#include <math_constants.h>
#include <cstdint>

#define NB 8
#define LL 1024
#define KNB 30
#define NRBF 16
#define EF 128
#define EIN 416
#define MAXREL 32

// Output layout (floats): h_V zeros | E | E_idx(float)
#define OFF_E    (NB*LL*EF)                       // 1,048,576
#define OFF_EIDX (OFF_E + (size_t)NB*LL*KNB*EF)   // 32,505,856

__device__ float g_Cb[NB*LL*3];
__device__ int   g_Eidx[NB*LL*KNB];
__device__ float g_Dn[NB*LL*KNB];

// atom codes: 0=N,1=Ca,2=C,3=O,4=Cb ; 24 pairs (A at i, B at j)
__constant__ int c_pa[24] = {0,2,3,4,1,1,1,1,0,0,0,4,4,3,0,2,3,4,2,3,4,2,3,2};
__constant__ int c_pb[24] = {0,2,3,4,0,2,3,4,2,3,4,2,3,2,1,1,1,1,0,0,0,4,4,3};

__global__ void zero_hv_kernel(float4* out) {
    int i = blockIdx.x * blockDim.x + threadIdx.x;
    if (i < NB*LL*EF/4) out[i] = make_float4(0.f,0.f,0.f,0.f);
}

__global__ void cb_kernel(const float* __restrict__ X) {
    int i = blockIdx.x * blockDim.x + threadIdx.x;
    if (i >= NB*LL) return;
    const float* x = X + (size_t)i * 12;
    float bx = x[3]-x[0], by = x[4]-x[1], bz = x[5]-x[2];
    float cx = x[6]-x[3], cy = x[7]-x[4], cz = x[8]-x[5];
    float ax = by*cz - bz*cy;
    float ay = bz*cx - bx*cz;
    float az = bx*cy - by*cx;
    g_Cb[i*3+0] = -0.58273431f*ax + 0.56802827f*bx - 0.54067466f*cx + x[3];
    g_Cb[i*3+1] = -0.58273431f*ay + 0.56802827f*by - 0.54067466f*cy + x[4];
    g_Cb[i*3+2] = -0.58273431f*az + 0.56802827f*bz - 0.54067466f*cz + x[5];
}

// ---------------- top-k: one WARP per row, keys in registers ----------------
__global__ void __launch_bounds__(256) topk_kernel(const float* __restrict__ X,
                                                   const float* __restrict__ mask,
                                                   float* __restrict__ out) {
    __shared__ float sx[LL], sy[LL], sz[LL], smk[LL];
    int tid = threadIdx.x;
    int rowBase = blockIdx.x * 8;
    int bb = rowBase >> 10;

    for (int j = tid; j < LL; j += 256) {
        const float* x = X + (size_t)(bb*LL + j) * 12;
        sx[j] = x[3]; sy[j] = x[4]; sz[j] = x[5];
        smk[j] = mask[bb*LL + j];
    }
    __syncthreads();

    int wid = tid >> 5, lane = tid & 31;
    int row = rowBase + wid;
    int i = row & 1023;
    float cx = sx[i], cy = sy[i], cz = sz[i], mi = smk[i];

    float D[32];
    float lmax = -CUDART_INF_F;
    #pragma unroll
    for (int q = 0; q < 32; q++) {
        int j = q*32 + lane;
        float dx = sx[j]-cx, dy = sy[j]-cy, dz = sz[j]-cz;
        float Dv = mi * smk[j] * sqrtf(dx*dx + dy*dy + dz*dz + 1e-6f);
        D[q] = Dv;
        lmax = fmaxf(lmax, Dv);
    }
    #pragma unroll
    for (int o = 16; o; o >>= 1)
        lmax = fmaxf(lmax, __shfl_xor_sync(0xffffffffu, lmax, o));

    unsigned long long key[32];
    #pragma unroll
    for (int q = 0; q < 32; q++) {
        int j = q*32 + lane;
        float adj = D[q] + (1.0f - mi*smk[j]) * lmax;
        key[q] = ((unsigned long long)__float_as_uint(adj) << 32) | (unsigned)j;
    }

    unsigned long long prevP1 = 0ull;
    for (int kn = 0; kn < KNB; kn++) {
        unsigned long long best = ~0ull;
        #pragma unroll
        for (int q = 0; q < 32; q++) {
            unsigned long long k = key[q];
            if (k >= prevP1 && k < best) best = k;
        }
        #pragma unroll
        for (int o = 16; o; o >>= 1) {
            unsigned long long other = __shfl_xor_sync(0xffffffffu, best, o);
            if (other < best) best = other;
        }
        if (lane == 0) {
            int j = (int)(best & 0xffffffffull);
            g_Eidx[row*KNB + kn] = j;
            g_Dn[row*KNB + kn]   = __uint_as_float((unsigned)(best >> 32));
            out[OFF_EIDX + (size_t)row*KNB + kn] = (float)j;
        }
        prevP1 = best + 1ull;
    }
}

__device__ __forceinline__ void load_atom(const float* __restrict__ X, int code, int gr,
                                          float& x, float& y, float& z) {
    if (code == 4) {
        const float* p = g_Cb + (size_t)gr*3;
        x = p[0]; y = p[1]; z = p[2];
    } else {
        const float* p = X + (size_t)gr*12 + code*3;
        x = p[0]; y = p[1]; z = p[2];
    }
}

#define FMA2(acc, w, e) asm("fma.rn.f32x2 %0, %1, %2, %0;" : "+l"(acc) : "l"(w), "l"(e))
#define PACK2(dst, s)   asm("mov.b64 %0, {%1, %1};" : "=l"(dst) : "r"(__float_as_uint(s)))

// ---------------- edge kernel: 1 residue/block, 2 blocks/SM ----------------
// smem: ed[16 pairs][417 doubles] = 53,376 B ; Wt[64 cols][132 floats] = 33,792 B
// WT_PAD must be a multiple of 4: phase B does LDS.128 at Wt + cc*WT_PAD + fg*4.
#define EDS 417
#define WT_PAD 132
#define ED_FLOATS (16*EDS*2)                       // 13,344 floats
#define SMEM_BYTES ((ED_FLOATS + 64*WT_PAD)*4)     // 87,168 B

__global__ void __launch_bounds__(256, 2) edge_kernel(
    const float* __restrict__ X,
    const int*   __restrict__ ridx,
    const int*   __restrict__ chain,
    const float* __restrict__ posW,
    const float* __restrict__ posb,
    const float* __restrict__ W,
    const float* __restrict__ gamma,
    const float* __restrict__ beta,
    float* __restrict__ out)
{
    extern __shared__ float smem[];
    float* Wt = smem + ED_FLOATS;
    int tid = threadIdx.x;
    int rg  = blockIdx.x;            // residue (b*L+i)
    int bb  = rg >> 10;

    // ---- Phase A: RBF features (30 * 25 = 750 tasks) ----
    for (int t = tid; t < 750; t += 256) {
        int kn = t / 25;
        int p  = t - kn*25;
        int j  = g_Eidx[rg*KNB + kn];
        float d;
        if (p == 0) {
            d = g_Dn[rg*KNB + kn];
        } else {
            float ax, ay, az, bx, by, bz;
            load_atom(X, c_pa[p-1], rg, ax, ay, az);
            load_atom(X, c_pb[p-1], bb*LL + j, bx, by, bz);
            float dx = ax-bx, dy = ay-by, dz = az-bz;
            d = sqrtf(dx*dx + dy*dy + dz*dz + 1e-6f);
        }
        int cbase = 16 + p*16;
        int pp = kn >> 1, sub = kn & 1;
        float* dst = smem + (size_t)(pp*EDS + cbase)*2 + sub;
        #pragma unroll
        for (int m = 0; m < NRBF; m++) {
            float z = (d - (2.0f + 1.3333333333f*m)) * 0.8f;
            dst[2*m] = __expf(-z*z);
        }
    }
    // ---- Phase A2: positional features (30 tasks) ----
    for (int t = tid; t < 30; t += 256) {
        int kn = t;
        int j  = g_Eidx[rg*KNB + kn];
        int gj = bb*LL + j;
        int dch = (chain[rg] == chain[gj]);
        int off = ridx[rg] - ridx[gj] + MAXREL;
        int dd  = dch ? min(max(off, 0), 2*MAXREL) : (2*MAXREL + 1);
        int pp = kn >> 1, sub = kn & 1;
        float* dst = smem + (size_t)(pp*EDS)*2 + sub;
        #pragma unroll
        for (int m = 0; m < 16; m++)
            dst[2*m] = posW[m*66 + dd] + posb[m];
    }
    // ---- zero pad pair 15 ----
    for (int idx = tid; idx < EDS*2; idx += 256)
        smem[15*EDS*2 + idx] = 0.0f;

    // ---- Phase B: GEMM. thread = (fg: 32 x F=4 feats, pg: 8 x P=2 pairs) ----
    int fg = tid >> 3;     // 0..31
    int pg = tid & 7;      // 0..7 -> pairs pg*2, pg*2+1
    unsigned long long acc[4][2];
    #pragma unroll
    for (int a = 0; a < 4; a++) { acc[a][0] = 0ull; acc[a][1] = 0ull; }

    const unsigned long long* e0 = (const unsigned long long*)smem + (size_t)(pg*2  )*EDS;
    const unsigned long long* e1 = (const unsigned long long*)smem + (size_t)(pg*2+1)*EDS;

    for (int ch = 0; ch < 7; ch++) {
        int c0  = ch * 64;
        int csz = (ch == 6) ? 32 : 64;
        __syncthreads();    // protect Wt from previous chunk's readers
        // load+transpose W chunk into Wt
        if (csz == 64) {
            for (int idx = tid; idx < 2048; idx += 256) {
                int f = idx >> 4, q = idx & 15;
                float4 v = *(const float4*)(W + (size_t)f*EIN + c0 + 4*q);
                float* wcol = Wt + (size_t)(4*q)*WT_PAD + f;
                wcol[0*WT_PAD] = v.x;
                wcol[1*WT_PAD] = v.y;
                wcol[2*WT_PAD] = v.z;
                wcol[3*WT_PAD] = v.w;
            }
        } else {
            for (int idx = tid; idx < 1024; idx += 256) {
                int f = idx >> 3, q = idx & 7;
                float4 v = *(const float4*)(W + (size_t)f*EIN + c0 + 4*q);
                float* wcol = Wt + (size_t)(4*q)*WT_PAD + f;
                wcol[0*WT_PAD] = v.x;
                wcol[1*WT_PAD] = v.y;
                wcol[2*WT_PAD] = v.z;
                wcol[3*WT_PAD] = v.w;
            }
        }
        __syncthreads();

        const float* wbase = Wt + fg*4;
        #pragma unroll 8
        for (int cc = 0; cc < csz; cc++) {
            float4 w4 = *(const float4*)(wbase + cc*WT_PAD);
            unsigned long long ea = e0[c0 + cc];
            unsigned long long eb = e1[c0 + cc];
            unsigned long long w0, w1, w2, w3;
            PACK2(w0, w4.x); PACK2(w1, w4.y); PACK2(w2, w4.z); PACK2(w3, w4.w);
            FMA2(acc[0][0], w0, ea);  FMA2(acc[0][1], w0, eb);
            FMA2(acc[1][0], w1, ea);  FMA2(acc[1][1], w1, eb);
            FMA2(acc[2][0], w2, ea);  FMA2(acc[2][1], w2, eb);
            FMA2(acc[3][0], w3, ea);  FMA2(acc[3][1], w3, eb);
        }
    }
    __syncthreads();

    // ---- write per-edge outputs to smem (reuse ed region): sout[30][128] ----
    float* sout = smem;
    #pragma unroll
    for (int pu = 0; pu < 2; pu++) {
        int p2 = pg*2 + pu;
        if (p2 < 15) {
            #pragma unroll
            for (int fu = 0; fu < 4; fu++) {
                unsigned lo = (unsigned)(acc[fu][pu] & 0xffffffffull);
                unsigned hi = (unsigned)(acc[fu][pu] >> 32);
                int f = fg*4 + fu;
                sout[(2*p2    )*EF + f] = __uint_as_float(lo);
                sout[(2*p2 + 1)*EF + f] = __uint_as_float(hi);
            }
        }
    }
    __syncthreads();

    // ---- LayerNorm + store: 8 warps over 30 edges ----
    int wr = tid >> 5, lane = tid & 31;
    for (int e = wr; e < 30; e += 8) {
        float x0 = sout[e*EF + lane];
        float x1 = sout[e*EF + lane + 32];
        float x2 = sout[e*EF + lane + 64];
        float x3 = sout[e*EF + lane + 96];
        float s = x0 + x1 + x2 + x3;
        #pragma unroll
        for (int o = 16; o; o >>= 1) s += __shfl_xor_sync(0xffffffffu, s, o);
        float mu = s * (1.0f/128.0f);
        float d0 = x0-mu, d1 = x1-mu, d2 = x2-mu, d3 = x3-mu;
        float vs = d0*d0 + d1*d1 + d2*d2 + d3*d3;
        #pragma unroll
        for (int o = 16; o; o >>= 1) vs += __shfl_xor_sync(0xffffffffu, vs, o);
        float inv = 1.0f / sqrtf(vs * (1.0f/128.0f) + 1e-5f);
        size_t base = OFF_E + ((size_t)rg*KNB + e)*EF;
        out[base + lane     ] = d0*inv*gamma[lane     ] + beta[lane     ];
        out[base + lane + 32] = d1*inv*gamma[lane + 32] + beta[lane + 32];
        out[base + lane + 64] = d2*inv*gamma[lane + 64] + beta[lane + 64];
        out[base + lane + 96] = d3*inv*gamma[lane + 96] + beta[lane + 96];
    }
}

extern "C" void kernel_launch(void* const* d_in, const int* in_sizes, int n_in,
                              void* d_out, int out_size) {
    const float* X     = (const float*)d_in[0];
    const float* mask  = (const float*)d_in[1];
    const int*   ridx  = (const int*)  d_in[2];
    const int*   chain = (const int*)  d_in[3];
    const float* posW  = (const float*)d_in[4];
    const float* posb  = (const float*)d_in[5];
    const float* W     = (const float*)d_in[6];
    const float* gamma = (const float*)d_in[7];
    const float* beta  = (const float*)d_in[8];
    float* out = (float*)d_out;

    zero_hv_kernel<<<(NB*LL*EF/4 + 255)/256, 256>>>((float4*)out);
    cb_kernel<<<(NB*LL + 255)/256, 256>>>(X);
    topk_kernel<<<NB*LL/8, 256>>>(X, mask, out);

    static bool attr_set = false;
    if (!attr_set) {
        cudaFuncSetAttribute(edge_kernel, cudaFuncAttributeMaxDynamicSharedMemorySize, SMEM_BYTES);
        attr_set = true;
    }
    edge_kernel<<<NB*LL, 256, SMEM_BYTES>>>(X, ridx, chain, posW, posb, W, gamma, beta, out);
}

// round 5
// speedup vs baseline: 1.8296x; 1.5015x over previous
#include <cuda_runtime.h>
#include <math_constants.h>
#include <cstdint>

#define NB 8
#define LL 1024
#define KNB 30
#define NRBF 16
#define EF 128
#define EIN 416
#define MAXREL 32

// Output layout (floats): h_V zeros | E | E_idx(float)
#define OFF_E    (NB*LL*EF)                       // 1,048,576
#define OFF_EIDX (OFF_E + (size_t)NB*LL*KNB*EF)   // 32,505,856

__device__ float g_Cb[NB*LL*3];
__device__ int   g_Eidx[NB*LL*KNB];
__device__ float g_Dn[NB*LL*KNB];
__device__ float g_Wt[EIN*EF];     // transposed W: g_Wt[c][f]

// atom codes: 0=N,1=Ca,2=C,3=O,4=Cb ; 24 pairs (A at i, B at j)
__constant__ int c_pa[24] = {0,2,3,4,1,1,1,1,0,0,0,4,4,3,0,2,3,4,2,3,4,2,3,2};
__constant__ int c_pb[24] = {0,2,3,4,0,2,3,4,2,3,4,2,3,2,1,1,1,1,0,0,0,4,4,3};

__global__ void zero_hv_kernel(float4* out) {
    int i = blockIdx.x * blockDim.x + threadIdx.x;
    if (i < NB*LL*EF/4) out[i] = make_float4(0.f,0.f,0.f,0.f);
}

__global__ void wt_kernel(const float* __restrict__ W) {
    int i = blockIdx.x * blockDim.x + threadIdx.x;   // over 416*128
    if (i >= EIN*EF) return;
    int c = i >> 7, f = i & 127;
    g_Wt[c*EF + f] = W[(size_t)f*EIN + c];
}

__global__ void cb_kernel(const float* __restrict__ X) {
    int i = blockIdx.x * blockDim.x + threadIdx.x;
    if (i >= NB*LL) return;
    const float* x = X + (size_t)i * 12;
    float bx = x[3]-x[0], by = x[4]-x[1], bz = x[5]-x[2];
    float cx = x[6]-x[3], cy = x[7]-x[4], cz = x[8]-x[5];
    float ax = by*cz - bz*cy;
    float ay = bz*cx - bx*cz;
    float az = bx*cy - by*cx;
    g_Cb[i*3+0] = -0.58273431f*ax + 0.56802827f*bx - 0.54067466f*cx + x[3];
    g_Cb[i*3+1] = -0.58273431f*ay + 0.56802827f*by - 0.54067466f*cy + x[4];
    g_Cb[i*3+2] = -0.58273431f*az + 0.56802827f*bz - 0.54067466f*cz + x[5];
}

// ---------------- top-k: one WARP per row, keys in registers ----------------
__global__ void __launch_bounds__(256) topk_kernel(const float* __restrict__ X,
                                                   const float* __restrict__ mask,
                                                   float* __restrict__ out) {
    __shared__ float sx[LL], sy[LL], sz[LL], smk[LL];
    int tid = threadIdx.x;
    int rowBase = blockIdx.x * 8;
    int bb = rowBase >> 10;

    for (int j = tid; j < LL; j += 256) {
        const float* x = X + (size_t)(bb*LL + j) * 12;
        sx[j] = x[3]; sy[j] = x[4]; sz[j] = x[5];
        smk[j] = mask[bb*LL + j];
    }
    __syncthreads();

    int wid = tid >> 5, lane = tid & 31;
    int row = rowBase + wid;
    int i = row & 1023;
    float cx = sx[i], cy = sy[i], cz = sz[i], mi = smk[i];

    float D[32];
    float lmax = -CUDART_INF_F;
    #pragma unroll
    for (int q = 0; q < 32; q++) {
        int j = q*32 + lane;
        float dx = sx[j]-cx, dy = sy[j]-cy, dz = sz[j]-cz;
        float Dv = mi * smk[j] * sqrtf(dx*dx + dy*dy + dz*dz + 1e-6f);
        D[q] = Dv;
        lmax = fmaxf(lmax, Dv);
    }
    #pragma unroll
    for (int o = 16; o; o >>= 1)
        lmax = fmaxf(lmax, __shfl_xor_sync(0xffffffffu, lmax, o));

    unsigned long long key[32];
    #pragma unroll
    for (int q = 0; q < 32; q++) {
        int j = q*32 + lane;
        float adj = D[q] + (1.0f - mi*smk[j]) * lmax;
        key[q] = ((unsigned long long)__float_as_uint(adj) << 32) | (unsigned)j;
    }

    unsigned long long prevP1 = 0ull;
    for (int kn = 0; kn < KNB; kn++) {
        unsigned long long best = ~0ull;
        #pragma unroll
        for (int q = 0; q < 32; q++) {
            unsigned long long k = key[q];
            if (k >= prevP1 && k < best) best = k;
        }
        #pragma unroll
        for (int o = 16; o; o >>= 1) {
            unsigned long long other = __shfl_xor_sync(0xffffffffu, best, o);
            if (other < best) best = other;
        }
        if (lane == 0) {
            int j = (int)(best & 0xffffffffull);
            g_Eidx[row*KNB + kn] = j;
            g_Dn[row*KNB + kn]   = __uint_as_float((unsigned)(best >> 32));
            out[OFF_EIDX + (size_t)row*KNB + kn] = (float)j;
        }
        prevP1 = best + 1ull;
    }
}

__device__ __forceinline__ void load_atom(const float* __restrict__ X, int code, int gr,
                                          float& x, float& y, float& z) {
    if (code == 4) {
        const float* p = g_Cb + (size_t)gr*3;
        x = p[0]; y = p[1]; z = p[2];
    } else {
        const float* p = X + (size_t)gr*12 + code*3;
        x = p[0]; y = p[1]; z = p[2];
    }
}

#define FMA2(acc, w, e) asm("fma.rn.f32x2 %0, %1, %2, %0;" : "+l"(acc) : "l"(w), "l"(e))
#define PACK2(dst, s)   asm("mov.b64 %0, {%1, %1};" : "=l"(dst) : "r"(__float_as_uint(s)))

// ---------------- edge kernel: 1 residue/block, 2 blocks/SM ----------------
// smem: ed col-major [416 cols][32 floats (30 edges + 2 pad)] = 53,248 B
//       Ws [64 cols][128 floats] = 32,768 B.   Total 86,016 B.
// ed float layout: smem[c*32 + kn]  (kn = edge index; f32x2 pair pp = kn>>1)
#define ED_FLOATS (EIN*32)                          // 13,312 floats
#define SMEM_BYTES ((ED_FLOATS + 64*EF)*4)          // 86,016 B

__global__ void __launch_bounds__(256, 2) edge_kernel(
    const float* __restrict__ X,
    const int*   __restrict__ ridx,
    const int*   __restrict__ chain,
    const float* __restrict__ posW,
    const float* __restrict__ posb,
    const float* __restrict__ gamma,
    const float* __restrict__ beta,
    float* __restrict__ out)
{
    extern __shared__ float smem[];
    float* Ws = smem + ED_FLOATS;
    int tid = threadIdx.x;
    int rg  = blockIdx.x;            // residue (b*L+i)
    int bb  = rg >> 10;

    // ---- zero ed (pad lanes 30,31 must be 0) ----
    {
        float4* p = (float4*)smem;
        for (int i = tid; i < ED_FLOATS/4; i += 256)
            p[i] = make_float4(0.f,0.f,0.f,0.f);
    }
    __syncthreads();

    // ---- Phase A: RBF features. t = p*30 + kn (kn fast -> bank-spread STS) ----
    for (int t = tid; t < 750; t += 256) {
        int p  = t / 30;
        int kn = t - p*30;
        int j  = g_Eidx[rg*KNB + kn];
        float d;
        if (p == 0) {
            d = g_Dn[rg*KNB + kn];
        } else {
            float ax, ay, az, bx, by, bz;
            load_atom(X, c_pa[p-1], rg, ax, ay, az);
            load_atom(X, c_pb[p-1], bb*LL + j, bx, by, bz);
            float dx = ax-bx, dy = ay-by, dz = az-bz;
            d = sqrtf(dx*dx + dy*dy + dz*dz + 1e-6f);
        }
        int cbase = 16 + p*16;
        float* dst = smem + (size_t)cbase*32 + kn;
        #pragma unroll
        for (int m = 0; m < NRBF; m++) {
            float z = (d - (2.0f + 1.3333333333f*m)) * 0.8f;
            dst[m*32] = __expf(-z*z);
        }
    }
    // ---- Phase A2: positional features (cols 0..15) ----
    for (int kn = tid; kn < 30; kn += 256) {
        int j  = g_Eidx[rg*KNB + kn];
        int gj = bb*LL + j;
        int dch = (chain[rg] == chain[gj]);
        int off = ridx[rg] - ridx[gj] + MAXREL;
        int dd  = dch ? min(max(off, 0), 2*MAXREL) : (2*MAXREL + 1);
        float* dst = smem + kn;
        #pragma unroll
        for (int m = 0; m < 16; m++)
            dst[m*32] = posW[m*66 + dd] + posb[m];
    }

    // ---- Phase B: GEMM. thread = (fg: 32 groups x F=4, pg: 8 groups x P=2) ----
    int fg = tid >> 3;     // 0..31 -> feats fg*4..fg*4+3
    int pg = tid & 7;      // 0..7  -> f32x2 pairs pg*2, pg*2+1
    unsigned long long acc[4][2];
    #pragma unroll
    for (int a = 0; a < 4; a++) { acc[a][0] = 0ull; acc[a][1] = 0ull; }

    for (int ch = 0; ch < 7; ch++) {
        int c0  = ch * 64;
        int csz = (ch == 6) ? 32 : 64;
        __syncthreads();    // Ws reuse safety
        // stage g_Wt chunk: fully coalesced LDG.128 -> STS.128, conflict-free
        {
            const float4* src = (const float4*)(g_Wt + (size_t)c0*EF);
            float4* dst = (float4*)Ws;
            int n4 = csz * (EF/4);
            for (int i = tid; i < n4; i += 256) dst[i] = src[i];
        }
        __syncthreads();

        const float* wbase = Ws + fg*4;
        const unsigned long long* ebase = (const unsigned long long*)smem + (size_t)c0*16 + pg*2;
        #pragma unroll 4
        for (int cc = 0; cc < csz; cc++) {
            float4 w4 = *(const float4*)(wbase + cc*EF);
            ulonglong2 e = *(const ulonglong2*)(ebase + cc*16);
            unsigned long long w0, w1, w2, w3;
            PACK2(w0, w4.x); PACK2(w1, w4.y); PACK2(w2, w4.z); PACK2(w3, w4.w);
            FMA2(acc[0][0], w0, e.x);  FMA2(acc[0][1], w0, e.y);
            FMA2(acc[1][0], w1, e.x);  FMA2(acc[1][1], w1, e.y);
            FMA2(acc[2][0], w2, e.x);  FMA2(acc[2][1], w2, e.y);
            FMA2(acc[3][0], w3, e.x);  FMA2(acc[3][1], w3, e.y);
        }
    }
    __syncthreads();

    // ---- write per-edge outputs to smem (reuse ed region): sout[30][128] ----
    float* sout = smem;
    #pragma unroll
    for (int pu = 0; pu < 2; pu++) {
        int p2 = pg*2 + pu;          // pair index 0..15
        if (p2 < 15) {
            #pragma unroll
            for (int fu = 0; fu < 4; fu++) {
                unsigned lo = (unsigned)(acc[fu][pu] & 0xffffffffull);
                unsigned hi = (unsigned)(acc[fu][pu] >> 32);
                int f = fg*4 + fu;
                sout[(2*p2    )*EF + f] = __uint_as_float(lo);
                sout[(2*p2 + 1)*EF + f] = __uint_as_float(hi);
            }
        }
    }
    __syncthreads();

    // ---- LayerNorm + store: 8 warps over 30 edges ----
    int wr = tid >> 5, lane = tid & 31;
    for (int e = wr; e < 30; e += 8) {
        float x0 = sout[e*EF + lane];
        float x1 = sout[e*EF + lane + 32];
        float x2 = sout[e*EF + lane + 64];
        float x3 = sout[e*EF + lane + 96];
        float s = x0 + x1 + x2 + x3;
        #pragma unroll
        for (int o = 16; o; o >>= 1) s += __shfl_xor_sync(0xffffffffu, s, o);
        float mu = s * (1.0f/128.0f);
        float d0 = x0-mu, d1 = x1-mu, d2 = x2-mu, d3 = x3-mu;
        float vs = d0*d0 + d1*d1 + d2*d2 + d3*d3;
        #pragma unroll
        for (int o = 16; o; o >>= 1) vs += __shfl_xor_sync(0xffffffffu, vs, o);
        float inv = 1.0f / sqrtf(vs * (1.0f/128.0f) + 1e-5f);
        size_t base = OFF_E + ((size_t)rg*KNB + e)*EF;
        out[base + lane     ] = d0*inv*gamma[lane     ] + beta[lane     ];
        out[base + lane + 32] = d1*inv*gamma[lane + 32] + beta[lane + 32];
        out[base + lane + 64] = d2*inv*gamma[lane + 64] + beta[lane + 64];
        out[base + lane + 96] = d3*inv*gamma[lane + 96] + beta[lane + 96];
    }
}

extern "C" void kernel_launch(void* const* d_in, const int* in_sizes, int n_in,
                              void* d_out, int out_size) {
    const float* X     = (const float*)d_in[0];
    const float* mask  = (const float*)d_in[1];
    const int*   ridx  = (const int*)  d_in[2];
    const int*   chain = (const int*)  d_in[3];
    const float* posW  = (const float*)d_in[4];
    const float* posb  = (const float*)d_in[5];
    const float* W     = (const float*)d_in[6];
    const float* gamma = (const float*)d_in[7];
    const float* beta  = (const float*)d_in[8];
    float* out = (float*)d_out;

    zero_hv_kernel<<<(NB*LL*EF/4 + 255)/256, 256>>>((float4*)out);
    wt_kernel<<<(EIN*EF + 255)/256, 256>>>(W);
    cb_kernel<<<(NB*LL + 255)/256, 256>>>(X);
    topk_kernel<<<NB*LL/8, 256>>>(X, mask, out);

    static bool attr_set = false;
    if (!attr_set) {
        cudaFuncSetAttribute(edge_kernel, cudaFuncAttributeMaxDynamicSharedMemorySize, SMEM_BYTES);
        attr_set = true;
    }
    edge_kernel<<<NB*LL, 256, SMEM_BYTES>>>(X, ridx, chain, posW, posb, gamma, beta, out);
}